// round 14
// baseline (speedup 1.0000x reference)
#include <cuda_runtime.h>
#include <cuda_bf16.h>
#include <cstdint>

#define DD 400
#define LC 2048
#define LA 512
#define NB 64

#define BM 128
#define BN 64
#define BK 32
#define NCH 13            // ceil(400/32) -> K padded to 416
#define KPAD 416

// smem layout (bytes). bf16 tiles with 80B row stride (64B data + 16B pad).
// 20-bank row stride => any 8 consecutive rows hit distinct bank groups in the
// ldmatrix quarter-warp phases: conflict-free without an xor swizzle.
#define ROWB 80
#define A_TILE (BM * ROWB)          // 10240
#define B_TILE (BN * ROWB)          // 5120
#define STAGE  (2 * A_TILE + 2 * B_TILE)   // 30720: Ahi, Alo, Bhi, Blo
#define OFF_AHI 0
#define OFF_ALO A_TILE
#define OFF_BHI (2 * A_TILE)
#define OFF_BLO (2 * A_TILE + B_TILE)
#define W_OFF   (2 * STAGE)                 // 61440
#define W_BYTES (KPAD * 4)                  // 1664 per vector
#define RT_OFF  (W_OFF + 3 * W_BYTES)       // 128 floats
#define CT_OFF  (RT_OFF + 512)              // 64 floats
#define SMEM_TOTAL (CT_OFF + 256)           // 66944 -> 2 CTAs/SM fit (134KB)

__device__ __forceinline__ uint32_t smem_u32(const void* p) {
    uint32_t a;
    asm("{ .reg .u64 t; cvta.to.shared.u64 t, %1; cvt.u32.u64 %0, t; }" : "=r"(a) : "l"(p));
    return a;
}

__device__ __forceinline__ void ldsm_x4(uint32_t& r0, uint32_t& r1, uint32_t& r2, uint32_t& r3,
                                        uint32_t addr) {
    asm volatile("ldmatrix.sync.aligned.m8n8.x4.shared.b16 {%0,%1,%2,%3}, [%4];"
                 : "=r"(r0), "=r"(r1), "=r"(r2), "=r"(r3) : "r"(addr));
}

__device__ __forceinline__ void mma_bf16(float* d, const uint32_t* a, uint32_t b0, uint32_t b1) {
    asm volatile(
        "mma.sync.aligned.m16n8k16.row.col.f32.bf16.bf16.f32 "
        "{%0,%1,%2,%3}, {%4,%5,%6,%7}, {%8,%9}, {%0,%1,%2,%3};"
        : "+f"(d[0]), "+f"(d[1]), "+f"(d[2]), "+f"(d[3])
        : "r"(a[0]), "r"(a[1]), "r"(a[2]), "r"(a[3]), "r"(b0), "r"(b1));
}

__device__ __forceinline__ uint32_t packbf(float a, float b) {
    __nv_bfloat162 h = __floats2bfloat162_rn(a, b);
    return *reinterpret_cast<uint32_t*>(&h);
}

// split 8 floats into bf16 hi (uint4) and bf16 lo (uint4)
__device__ __forceinline__ void split8(const float* f, uint4& hi, uint4& lo) {
    float h[8], l[8];
    #pragma unroll
    for (int j = 0; j < 8; j++) {
        h[j] = __bfloat162float(__float2bfloat16(f[j]));
        l[j] = f[j] - h[j];
    }
    hi = make_uint4(packbf(h[0], h[1]), packbf(h[2], h[3]), packbf(h[4], h[5]), packbf(h[6], h[7]));
    lo = make_uint4(packbf(l[0], l[1]), packbf(l[2], l[3]), packbf(l[4], l[5]), packbf(l[6], l[7]));
}

__global__ __launch_bounds__(256, 2)
void alignment_hmma_kernel(const float* __restrict__ ctx,
                           const float* __restrict__ asp,
                           const float* __restrict__ w_u,
                           float* __restrict__ out)
{
    extern __shared__ char sm[];
    const uint32_t smu = smem_u32(sm);

    const int tid  = threadIdx.x;
    const int w    = tid >> 5;
    const int lane = tid & 31;
    const int b    = blockIdx.z;
    const int rowTile = blockIdx.y * BM;
    const int colTile = blockIdx.x * BN;

    float* w1s = (float*)(sm + W_OFF);
    float* w2s = (float*)(sm + W_OFF + W_BYTES);
    float* w3s = (float*)(sm + W_OFF + 2 * W_BYTES);
    float* rt_s = (float*)(sm + RT_OFF);
    float* ct_s = (float*)(sm + CT_OFF);

    for (int i = tid; i < KPAD; i += 256) {
        bool v = i < DD;
        w1s[i] = v ? w_u[i]          : 0.f;
        w2s[i] = v ? w_u[DD + i]     : 0.f;
        w3s[i] = v ? w_u[2 * DD + i] : 0.f;
    }
    __syncthreads();

    // loader roles (asymmetric): A 128 rows x 2 halves, B 64 rows x 4 quarters
    const int arow  = tid >> 1;         // 0..127
    const int ahalf = tid & 1;          // 16 k-elems each
    const int brow  = tid >> 2;         // 0..63
    const int bq    = tid & 3;          // 8 k-elems each

    // hoisted row pointers (cuts per-chunk ALU)
    const float* ArowP = ctx + (size_t)b * LC * DD + (size_t)(rowTile + arow) * DD + ahalf * 16;
    const float* BrowP = asp + (size_t)b * LA * DD + (size_t)(colTile + brow) * DD + bq * 8;
    const uint32_t aSt = (uint32_t)(arow * ROWB + ahalf * 32);
    const uint32_t bSt = (uint32_t)(brow * ROWB + bq * 16);

    float rt_acc = 0.f, ct_acc = 0.f;

    float4 nA[4], nB[2];

    auto prefetch = [&](int c) {
        const int k0 = c * BK;
        #pragma unroll
        for (int i = 0; i < 4; i++) {
            int k = k0 + ahalf * 16 + i * 4;
            nA[i] = (k < DD) ? __ldg((const float4*)(ArowP + c * BK + i * 4))
                             : make_float4(0.f, 0.f, 0.f, 0.f);
        }
        #pragma unroll
        for (int i = 0; i < 2; i++) {
            int k = k0 + bq * 8 + i * 4;
            nB[i] = (k < DD) ? __ldg((const float4*)(BrowP + c * BK + i * 4))
                             : make_float4(0.f, 0.f, 0.f, 0.f);
        }
    };

    auto convert_store = [&](int c) {
        char* st = sm + (c & 1) * STAGE;
        const int k0 = c * BK;
        // A: fold w3, accumulate rt with w1
        #pragma unroll
        for (int g = 0; g < 2; g++) {
            const int kb = k0 + ahalf * 16 + g * 8;
            float f[8];
            f[0] = nA[2 * g].x; f[1] = nA[2 * g].y; f[2] = nA[2 * g].z; f[3] = nA[2 * g].w;
            f[4] = nA[2 * g + 1].x; f[5] = nA[2 * g + 1].y;
            f[6] = nA[2 * g + 1].z; f[7] = nA[2 * g + 1].w;
            #pragma unroll
            for (int j = 0; j < 8; j++) {
                rt_acc += f[j] * w1s[kb + j];
                f[j] *= w3s[kb + j];
            }
            uint4 hi, lo;
            split8(f, hi, lo);
            *(uint4*)(st + OFF_AHI + aSt + g * 16) = hi;
            *(uint4*)(st + OFF_ALO + aSt + g * 16) = lo;
        }
        // B: accumulate ct with w2
        {
            const int kb = k0 + bq * 8;
            float f[8];
            f[0] = nB[0].x; f[1] = nB[0].y; f[2] = nB[0].z; f[3] = nB[0].w;
            f[4] = nB[1].x; f[5] = nB[1].y; f[6] = nB[1].z; f[7] = nB[1].w;
            #pragma unroll
            for (int j = 0; j < 8; j++) ct_acc += f[j] * w2s[kb + j];
            uint4 hi, lo;
            split8(f, hi, lo);
            *(uint4*)(st + OFF_BHI + bSt) = hi;
            *(uint4*)(st + OFF_BLO + bSt) = lo;
        }
    };

    // mma thread geometry: 4(M) x 2(N) warps, warp tile 32x32
    const int warpMoff = (w & 3) * 32;
    const int warpNoff = (w >> 2) * 32;
    const int lr  = lane & 15;
    const int lkg = lane >> 4;

    float acc[2][4][4];
    #pragma unroll
    for (int mf = 0; mf < 2; mf++)
        #pragma unroll
        for (int nf = 0; nf < 4; nf++)
            #pragma unroll
            for (int i = 0; i < 4; i++) acc[mf][nf][i] = 0.f;

    prefetch(0);
    convert_store(0);
    __syncthreads();

    for (int c = 0; c < NCH; c++) {
        if (c + 1 < NCH) prefetch(c + 1);

        // ---- MMA over chunk c ----
        {
            const uint32_t st = smu + (uint32_t)(c & 1) * STAGE;
            #pragma unroll
            for (int ks = 0; ks < 2; ks++) {
                const uint32_t kg = (uint32_t)(ks * 2 + lkg);
                uint32_t ah[2][4], al[2][4], bh[2][4], bl[2][4];
                #pragma unroll
                for (int mf = 0; mf < 2; mf++) {
                    const int row = warpMoff + mf * 16 + lr;
                    const uint32_t off = (uint32_t)row * ROWB + kg * 16;
                    ldsm_x4(ah[mf][0], ah[mf][1], ah[mf][2], ah[mf][3], st + OFF_AHI + off);
                    ldsm_x4(al[mf][0], al[mf][1], al[mf][2], al[mf][3], st + OFF_ALO + off);
                }
                #pragma unroll
                for (int j = 0; j < 2; j++) {
                    const int row = warpNoff + j * 16 + lr;
                    const uint32_t off = (uint32_t)row * ROWB + kg * 16;
                    ldsm_x4(bh[j][0], bh[j][1], bh[j][2], bh[j][3], st + OFF_BHI + off);
                    ldsm_x4(bl[j][0], bl[j][1], bl[j][2], bl[j][3], st + OFF_BLO + off);
                }
                #pragma unroll
                for (int mf = 0; mf < 2; mf++) {
                    #pragma unroll
                    for (int j = 0; j < 2; j++) {
                        mma_bf16(acc[mf][2 * j],     ah[mf], bh[j][0], bh[j][2]);
                        mma_bf16(acc[mf][2 * j],     ah[mf], bl[j][0], bl[j][2]);
                        mma_bf16(acc[mf][2 * j],     al[mf], bh[j][0], bh[j][2]);
                        mma_bf16(acc[mf][2 * j + 1], ah[mf], bh[j][1], bh[j][3]);
                        mma_bf16(acc[mf][2 * j + 1], ah[mf], bl[j][1], bl[j][3]);
                        mma_bf16(acc[mf][2 * j + 1], al[mf], bh[j][1], bh[j][3]);
                    }
                }
            }
        }

        if (c + 1 < NCH) convert_store(c + 1);
        __syncthreads();
    }

    // ---- reduce rank-1 terms ----
    {
        float r = rt_acc + __shfl_xor_sync(0xffffffffu, rt_acc, 1);
        if (ahalf == 0) rt_s[arow] = r;
        float q = ct_acc + __shfl_xor_sync(0xffffffffu, ct_acc, 1);
        q += __shfl_xor_sync(0xffffffffu, q, 2);
        if (bq == 0) ct_s[brow] = q;
    }
    __syncthreads();

    // ---- epilogue ----
    float* Cg = out + ((size_t)b * LC + rowTile) * LA + colTile;
    #pragma unroll
    for (int mf = 0; mf < 2; mf++) {
        const int r0 = warpMoff + mf * 16 + (lane >> 2);
        const int r1 = r0 + 8;
        const float rt0 = rt_s[r0], rt1 = rt_s[r1];
        #pragma unroll
        for (int nf = 0; nf < 4; nf++) {
            const int c0 = warpNoff + nf * 8 + (lane & 3) * 2;
            const float ct0 = ct_s[c0], ct1 = ct_s[c0 + 1];
            float2 v0 = make_float2(acc[mf][nf][0] + rt0 + ct0, acc[mf][nf][1] + rt0 + ct1);
            float2 v1 = make_float2(acc[mf][nf][2] + rt1 + ct0, acc[mf][nf][3] + rt1 + ct1);
            *(float2*)(Cg + (size_t)r0 * LA + c0) = v0;
            *(float2*)(Cg + (size_t)r1 * LA + c0) = v1;
        }
    }
}

extern "C" void kernel_launch(void* const* d_in, const int* in_sizes, int n_in,
                              void* d_out, int out_size)
{
    const float* ctx = nullptr;
    const float* asp = nullptr;
    const float* w_u = nullptr;
    for (int i = 0; i < n_in; i++) {
        if (in_sizes[i] == NB * LC * DD)      ctx = (const float*)d_in[i];
        else if (in_sizes[i] == NB * LA * DD) asp = (const float*)d_in[i];
        else if (in_sizes[i] == 3 * DD)       w_u = (const float*)d_in[i];
    }
    float* out = (float*)d_out;

    cudaFuncSetAttribute(alignment_hmma_kernel,
                         cudaFuncAttributeMaxDynamicSharedMemorySize, SMEM_TOTAL);

    dim3 grid(LA / BN, LC / BM, NB);   // (8, 16, 64)
    alignment_hmma_kernel<<<grid, 256, SMEM_TOTAL>>>(ctx, asp, w_u, out);

    (void)out_size;
}

// round 15
// speedup vs baseline: 1.6200x; 1.6200x over previous
#include <cuda_runtime.h>
#include <cuda_bf16.h>
#include <cstdint>

#define DD 400
#define LC 2048
#define LA 512
#define NB 64

#define BM 128
#define BN 256
#define BK 32
#define NCH 13            // ceil(400/32) -> K padded to 416
#define KPAD 416

// smem layout (bytes). bf16 tiles with 80B row stride (64B data + 16B pad).
// 20-bank row stride => 8 consecutive rows in an ldmatrix phase hit distinct
// bank groups: conflict-free without an xor swizzle.
#define ROWB 80
#define A_TILE (BM * ROWB)          // 10240
#define B_TILE (BN * ROWB)          // 20480
#define STAGE  (2 * A_TILE + 2 * B_TILE)   // 61440: Ahi, Alo, Bhi, Blo
#define OFF_AHI 0
#define OFF_ALO A_TILE
#define OFF_BHI (2 * A_TILE)
#define OFF_BLO (2 * A_TILE + B_TILE)
#define W_OFF   (2 * STAGE)                 // 122880
#define W_BYTES (KPAD * 4)                  // 1664 per vector
#define RT_OFF  (W_OFF + 3 * W_BYTES)       // 128 floats
#define CT_OFF  (RT_OFF + 512)              // 256 floats
#define SMEM_TOTAL (CT_OFF + 1024)          // ~129.4KB -> 1 CTA/SM

__device__ __forceinline__ uint32_t smem_u32(const void* p) {
    uint32_t a;
    asm("{ .reg .u64 t; cvta.to.shared.u64 t, %1; cvt.u32.u64 %0, t; }" : "=r"(a) : "l"(p));
    return a;
}

__device__ __forceinline__ void ldsm_x4(uint32_t& r0, uint32_t& r1, uint32_t& r2, uint32_t& r3,
                                        uint32_t addr) {
    asm volatile("ldmatrix.sync.aligned.m8n8.x4.shared.b16 {%0,%1,%2,%3}, [%4];"
                 : "=r"(r0), "=r"(r1), "=r"(r2), "=r"(r3) : "r"(addr));
}

__device__ __forceinline__ void mma_bf16(float* d, const uint32_t* a, uint32_t b0, uint32_t b1) {
    asm volatile(
        "mma.sync.aligned.m16n8k16.row.col.f32.bf16.bf16.f32 "
        "{%0,%1,%2,%3}, {%4,%5,%6,%7}, {%8,%9}, {%0,%1,%2,%3};"
        : "+f"(d[0]), "+f"(d[1]), "+f"(d[2]), "+f"(d[3])
        : "r"(a[0]), "r"(a[1]), "r"(a[2]), "r"(a[3]), "r"(b0), "r"(b1));
}

__device__ __forceinline__ uint32_t packbf(float a, float b) {
    __nv_bfloat162 h = __floats2bfloat162_rn(a, b);
    return *reinterpret_cast<uint32_t*>(&h);
}

// split 8 floats into bf16 hi (uint4) and bf16 lo (uint4)
__device__ __forceinline__ void split8(const float* f, uint4& hi, uint4& lo) {
    float h[8], l[8];
    #pragma unroll
    for (int j = 0; j < 8; j++) {
        h[j] = __bfloat162float(__float2bfloat16(f[j]));
        l[j] = f[j] - h[j];
    }
    hi = make_uint4(packbf(h[0], h[1]), packbf(h[2], h[3]), packbf(h[4], h[5]), packbf(h[6], h[7]));
    lo = make_uint4(packbf(l[0], l[1]), packbf(l[2], l[3]), packbf(l[4], l[5]), packbf(l[6], l[7]));
}

__global__ __launch_bounds__(512, 1)
void alignment_hmma_kernel(const float* __restrict__ ctx,
                           const float* __restrict__ asp,
                           const float* __restrict__ w_u,
                           float* __restrict__ out)
{
    extern __shared__ char sm[];
    const uint32_t smu = smem_u32(sm);

    const int tid  = threadIdx.x;
    const int w    = tid >> 5;
    const int lane = tid & 31;
    const int b    = blockIdx.z;
    const int rowTile = blockIdx.y * BM;
    const int colTile = blockIdx.x * BN;

    float* w1s = (float*)(sm + W_OFF);
    float* w2s = (float*)(sm + W_OFF + W_BYTES);
    float* w3s = (float*)(sm + W_OFF + 2 * W_BYTES);
    float* rt_s = (float*)(sm + RT_OFF);
    float* ct_s = (float*)(sm + CT_OFF);

    for (int i = tid; i < KPAD; i += 512) {
        bool v = i < DD;
        w1s[i] = v ? w_u[i]          : 0.f;
        w2s[i] = v ? w_u[DD + i]     : 0.f;
        w3s[i] = v ? w_u[2 * DD + i] : 0.f;
    }
    __syncthreads();

    // loader roles: A 128 rows x 4 quarters (8 k each); B 256 rows x 2 halves (16 k each)
    const int arow  = tid >> 2;         // 0..127
    const int aq    = tid & 3;          // 8 k-elems
    const int brow  = tid >> 1;         // 0..255
    const int bhalf = tid & 1;          // 16 k-elems

    const float* ArowP = ctx + (size_t)b * LC * DD + (size_t)(rowTile + arow) * DD + aq * 8;
    const float* BrowP = asp + (size_t)b * LA * DD + (size_t)(colTile + brow) * DD + bhalf * 16;
    const uint32_t aSt = (uint32_t)(arow * ROWB + aq * 16);
    const uint32_t bSt = (uint32_t)(brow * ROWB + bhalf * 32);

    float rt_acc = 0.f, ct_acc = 0.f;

    float4 nA[2], nB[4];

    auto prefetch = [&](int c) {
        const int k0 = c * BK;
        #pragma unroll
        for (int i = 0; i < 2; i++) {
            int k = k0 + aq * 8 + i * 4;
            nA[i] = (k < DD) ? __ldg((const float4*)(ArowP + c * BK + i * 4))
                             : make_float4(0.f, 0.f, 0.f, 0.f);
        }
        #pragma unroll
        for (int i = 0; i < 4; i++) {
            int k = k0 + bhalf * 16 + i * 4;
            nB[i] = (k < DD) ? __ldg((const float4*)(BrowP + c * BK + i * 4))
                             : make_float4(0.f, 0.f, 0.f, 0.f);
        }
    };

    auto convert_store = [&](int c) {
        char* st = sm + (c & 1) * STAGE;
        const int k0 = c * BK;
        // A: fold w3, accumulate rt with w1 (8 elems)
        {
            const int kb = k0 + aq * 8;
            float f[8];
            f[0] = nA[0].x; f[1] = nA[0].y; f[2] = nA[0].z; f[3] = nA[0].w;
            f[4] = nA[1].x; f[5] = nA[1].y; f[6] = nA[1].z; f[7] = nA[1].w;
            #pragma unroll
            for (int j = 0; j < 8; j++) {
                rt_acc += f[j] * w1s[kb + j];
                f[j] *= w3s[kb + j];
            }
            uint4 hi, lo;
            split8(f, hi, lo);
            *(uint4*)(st + OFF_AHI + aSt) = hi;
            *(uint4*)(st + OFF_ALO + aSt) = lo;
        }
        // B: accumulate ct with w2 (16 elems)
        #pragma unroll
        for (int g = 0; g < 2; g++) {
            const int kb = k0 + bhalf * 16 + g * 8;
            float f[8];
            f[0] = nB[2 * g].x; f[1] = nB[2 * g].y; f[2] = nB[2 * g].z; f[3] = nB[2 * g].w;
            f[4] = nB[2 * g + 1].x; f[5] = nB[2 * g + 1].y;
            f[6] = nB[2 * g + 1].z; f[7] = nB[2 * g + 1].w;
            #pragma unroll
            for (int j = 0; j < 8; j++) ct_acc += f[j] * w2s[kb + j];
            uint4 hi, lo;
            split8(f, hi, lo);
            *(uint4*)(st + OFF_BHI + bSt + g * 16) = hi;
            *(uint4*)(st + OFF_BLO + bSt + g * 16) = lo;
        }
    };

    // mma thread geometry: 4(M) x 4(N) warps, warp tile 32x64
    const int warpMoff = (w & 3) * 32;
    const int warpNoff = (w >> 2) * 64;
    const int lr  = lane & 15;
    const int lkg = lane >> 4;

    float acc[2][8][4];
    #pragma unroll
    for (int mf = 0; mf < 2; mf++)
        #pragma unroll
        for (int nf = 0; nf < 8; nf++)
            #pragma unroll
            for (int i = 0; i < 4; i++) acc[mf][nf][i] = 0.f;

    prefetch(0);
    convert_store(0);
    __syncthreads();

    for (int c = 0; c < NCH; c++) {
        if (c + 1 < NCH) prefetch(c + 1);

        // ---- MMA over chunk c ----
        {
            const uint32_t st = smu + (uint32_t)(c & 1) * STAGE;
            #pragma unroll
            for (int ks = 0; ks < 2; ks++) {
                const uint32_t kgo = (uint32_t)(ks * 2 + lkg) * 16;
                uint32_t ah[2][4], al[2][4];
                #pragma unroll
                for (int mf = 0; mf < 2; mf++) {
                    const uint32_t off = (uint32_t)(warpMoff + mf * 16 + lr) * ROWB + kgo;
                    ldsm_x4(ah[mf][0], ah[mf][1], ah[mf][2], ah[mf][3], st + OFF_AHI + off);
                    ldsm_x4(al[mf][0], al[mf][1], al[mf][2], al[mf][3], st + OFF_ALO + off);
                }
                #pragma unroll
                for (int j = 0; j < 4; j++) {
                    uint32_t bh[4], bl[4];
                    const uint32_t off = (uint32_t)(warpNoff + j * 16 + lr) * ROWB + kgo;
                    ldsm_x4(bh[0], bh[1], bh[2], bh[3], st + OFF_BHI + off);
                    ldsm_x4(bl[0], bl[1], bl[2], bl[3], st + OFF_BLO + off);
                    #pragma unroll
                    for (int mf = 0; mf < 2; mf++) {
                        mma_bf16(acc[mf][2 * j],     ah[mf], bh[0], bh[2]);
                        mma_bf16(acc[mf][2 * j],     ah[mf], bl[0], bl[2]);
                        mma_bf16(acc[mf][2 * j],     al[mf], bh[0], bh[2]);
                        mma_bf16(acc[mf][2 * j + 1], ah[mf], bh[1], bh[3]);
                        mma_bf16(acc[mf][2 * j + 1], ah[mf], bl[1], bl[3]);
                        mma_bf16(acc[mf][2 * j + 1], al[mf], bh[1], bh[3]);
                    }
                }
            }
        }

        if (c + 1 < NCH) convert_store(c + 1);
        __syncthreads();
    }

    // ---- reduce rank-1 terms ----
    {
        float r = rt_acc + __shfl_xor_sync(0xffffffffu, rt_acc, 1);
        r += __shfl_xor_sync(0xffffffffu, r, 2);
        if (aq == 0) rt_s[arow] = r;
        float q = ct_acc + __shfl_xor_sync(0xffffffffu, ct_acc, 1);
        if (bhalf == 0) ct_s[brow] = q;
    }
    __syncthreads();

    // ---- epilogue ----
    float* Cg = out + ((size_t)b * LC + rowTile) * LA + colTile;
    #pragma unroll
    for (int mf = 0; mf < 2; mf++) {
        const int r0 = warpMoff + mf * 16 + (lane >> 2);
        const int r1 = r0 + 8;
        const float rt0 = rt_s[r0], rt1 = rt_s[r1];
        #pragma unroll
        for (int nf = 0; nf < 8; nf++) {
            const int c0 = warpNoff + nf * 8 + (lane & 3) * 2;
            const float ct0 = ct_s[c0], ct1 = ct_s[c0 + 1];
            float2 v0 = make_float2(acc[mf][nf][0] + rt0 + ct0, acc[mf][nf][1] + rt0 + ct1);
            float2 v1 = make_float2(acc[mf][nf][2] + rt1 + ct0, acc[mf][nf][3] + rt1 + ct1);
            *(float2*)(Cg + (size_t)r0 * LA + c0) = v0;
            *(float2*)(Cg + (size_t)r1 * LA + c0) = v1;
        }
    }
}

extern "C" void kernel_launch(void* const* d_in, const int* in_sizes, int n_in,
                              void* d_out, int out_size)
{
    const float* ctx = nullptr;
    const float* asp = nullptr;
    const float* w_u = nullptr;
    for (int i = 0; i < n_in; i++) {
        if (in_sizes[i] == NB * LC * DD)      ctx = (const float*)d_in[i];
        else if (in_sizes[i] == NB * LA * DD) asp = (const float*)d_in[i];
        else if (in_sizes[i] == 3 * DD)       w_u = (const float*)d_in[i];
    }
    float* out = (float*)d_out;

    cudaFuncSetAttribute(alignment_hmma_kernel,
                         cudaFuncAttributeMaxDynamicSharedMemorySize, SMEM_TOTAL);

    dim3 grid(LA / BN, LC / BM, NB);   // (2, 16, 64)
    alignment_hmma_kernel<<<grid, 512, SMEM_TOTAL>>>(ctx, asp, w_u, out);

    (void)out_size;
}

// round 16
// speedup vs baseline: 1.9173x; 1.1835x over previous
#include <cuda_runtime.h>
#include <cuda_bf16.h>
#include <cstdint>

#define DD 400
#define LC 2048
#define LA 512
#define NB 64

#define BM 128
#define BN 128
#define BK 32
#define NCH 13            // ceil(400/32) -> K padded to 416
#define KPAD 416

// smem layout (bytes). bf16 tiles with 80B row stride (64B data + 16B pad).
#define ROWB 80
#define A_TILE (BM * ROWB)          // 10240
#define B_TILE (BN * ROWB)          // 10240
#define STAGE  (2 * A_TILE + 2 * B_TILE)   // 40960: Ahi, Alo, Bhi, Blo
#define OFF_AHI 0
#define OFF_ALO A_TILE
#define OFF_BHI (2 * A_TILE)
#define OFF_BLO (2 * A_TILE + B_TILE)
#define W_OFF   (2 * STAGE)                 // 81920
#define W_BYTES (KPAD * 4)                  // 1664 per vector
#define RT_OFF  (W_OFF + 3 * W_BYTES)       // 128 floats
#define CT_OFF  (RT_OFF + 512)              // 128 floats
#define SMEM_TOTAL (CT_OFF + 512)           // ~88KB -> 1 CTA/SM

__device__ __forceinline__ uint32_t smem_u32(const void* p) {
    uint32_t a;
    asm("{ .reg .u64 t; cvta.to.shared.u64 t, %1; cvt.u32.u64 %0, t; }" : "=r"(a) : "l"(p));
    return a;
}

__device__ __forceinline__ void ldsm_x4(uint32_t& r0, uint32_t& r1, uint32_t& r2, uint32_t& r3,
                                        uint32_t addr) {
    asm volatile("ldmatrix.sync.aligned.m8n8.x4.shared.b16 {%0,%1,%2,%3}, [%4];"
                 : "=r"(r0), "=r"(r1), "=r"(r2), "=r"(r3) : "r"(addr));
}

__device__ __forceinline__ void mma_bf16(float* d, const uint32_t* a, uint32_t b0, uint32_t b1) {
    asm volatile(
        "mma.sync.aligned.m16n8k16.row.col.f32.bf16.bf16.f32 "
        "{%0,%1,%2,%3}, {%4,%5,%6,%7}, {%8,%9}, {%0,%1,%2,%3};"
        : "+f"(d[0]), "+f"(d[1]), "+f"(d[2]), "+f"(d[3])
        : "r"(a[0]), "r"(a[1]), "r"(a[2]), "r"(a[3]), "r"(b0), "r"(b1));
}

__device__ __forceinline__ uint32_t packbf(float a, float b) {
    __nv_bfloat162 h = __floats2bfloat162_rn(a, b);
    return *reinterpret_cast<uint32_t*>(&h);
}

// split 8 floats into bf16 hi (uint4) and bf16 lo (uint4)
__device__ __forceinline__ void split8(const float* f, uint4& hi, uint4& lo) {
    float h[8], l[8];
    #pragma unroll
    for (int j = 0; j < 8; j++) {
        h[j] = __bfloat162float(__float2bfloat16(f[j]));
        l[j] = f[j] - h[j];
    }
    hi = make_uint4(packbf(h[0], h[1]), packbf(h[2], h[3]), packbf(h[4], h[5]), packbf(h[6], h[7]));
    lo = make_uint4(packbf(l[0], l[1]), packbf(l[2], l[3]), packbf(l[4], l[5]), packbf(l[6], l[7]));
}

__global__ __launch_bounds__(512, 1)
void alignment_hmma_kernel(const float* __restrict__ ctx,
                           const float* __restrict__ asp,
                           const float* __restrict__ w_u,
                           float* __restrict__ out)
{
    extern __shared__ char sm[];
    const uint32_t smu = smem_u32(sm);

    const int tid  = threadIdx.x;
    const int w    = tid >> 5;
    const int lane = tid & 31;
    const int b    = blockIdx.z;
    const int rowTile = blockIdx.y * BM;
    const int colTile = blockIdx.x * BN;

    float* w1s = (float*)(sm + W_OFF);
    float* w2s = (float*)(sm + W_OFF + W_BYTES);
    float* w3s = (float*)(sm + W_OFF + 2 * W_BYTES);
    float* rt_s = (float*)(sm + RT_OFF);
    float* ct_s = (float*)(sm + CT_OFF);

    for (int i = tid; i < KPAD; i += 512) {
        bool v = i < DD;
        w1s[i] = v ? w_u[i]          : 0.f;
        w2s[i] = v ? w_u[DD + i]     : 0.f;
        w3s[i] = v ? w_u[2 * DD + i] : 0.f;
    }
    __syncthreads();

    const bool isProducer = (w >= 8);

    if (isProducer) {
        // ================= PRODUCER (warps 8..15, 256 threads) =================
        const int ptid  = tid - 256;
        const int prow  = ptid >> 1;        // 0..127 (A row and B row)
        const int phalf = ptid & 1;         // which 16 k-elems

        const float* ArowP = ctx + (size_t)b * LC * DD + (size_t)(rowTile + prow) * DD + phalf * 16;
        const float* BrowP = asp + (size_t)b * LA * DD + (size_t)(colTile + prow) * DD + phalf * 16;
        const uint32_t pSt = (uint32_t)(prow * ROWB + phalf * 32);

        float rt_acc = 0.f, ct_acc = 0.f;

        float4 A0[4], B0[4], A1[4], B1[4];   // two explicit register sets

        auto prefetch = [&](int c, float4* A, float4* B) {
            #pragma unroll
            for (int i = 0; i < 4; i++) {
                int k = c * BK + phalf * 16 + i * 4;
                bool kv = k < DD;
                A[i] = kv ? __ldg((const float4*)(ArowP + c * BK + i * 4))
                          : make_float4(0.f, 0.f, 0.f, 0.f);
                B[i] = kv ? __ldg((const float4*)(BrowP + c * BK + i * 4))
                          : make_float4(0.f, 0.f, 0.f, 0.f);
            }
        };

        auto convert_store = [&](int c, const float4* A, const float4* B) {
            char* st = sm + (c & 1) * STAGE;
            #pragma unroll
            for (int g = 0; g < 2; g++) {
                const int kb = c * BK + phalf * 16 + g * 8;
                // A: fold w3, accumulate rt with w1
                {
                    float f[8];
                    f[0] = A[2 * g].x; f[1] = A[2 * g].y; f[2] = A[2 * g].z; f[3] = A[2 * g].w;
                    f[4] = A[2 * g + 1].x; f[5] = A[2 * g + 1].y;
                    f[6] = A[2 * g + 1].z; f[7] = A[2 * g + 1].w;
                    #pragma unroll
                    for (int j = 0; j < 8; j++) {
                        rt_acc += f[j] * w1s[kb + j];
                        f[j] *= w3s[kb + j];
                    }
                    uint4 hi, lo;
                    split8(f, hi, lo);
                    *(uint4*)(st + OFF_AHI + pSt + g * 16) = hi;
                    *(uint4*)(st + OFF_ALO + pSt + g * 16) = lo;
                }
                // B: accumulate ct with w2
                {
                    float f[8];
                    f[0] = B[2 * g].x; f[1] = B[2 * g].y; f[2] = B[2 * g].z; f[3] = B[2 * g].w;
                    f[4] = B[2 * g + 1].x; f[5] = B[2 * g + 1].y;
                    f[6] = B[2 * g + 1].z; f[7] = B[2 * g + 1].w;
                    #pragma unroll
                    for (int j = 0; j < 8; j++) ct_acc += f[j] * w2s[kb + j];
                    uint4 hi, lo;
                    split8(f, hi, lo);
                    *(uint4*)(st + OFF_BHI + pSt + g * 16) = hi;
                    *(uint4*)(st + OFF_BLO + pSt + g * 16) = lo;
                }
            }
        };

        // prologue: stage chunk 0, start LDG for chunk 1
        prefetch(0, A0, B0);
        convert_store(0, A0, B0);
        prefetch(1, A1, B1);
        __syncthreads();

        // 2x-unrolled steady state: chunks 0..11 MMA'd here, 12 staged at the end
        for (int c = 0; c + 2 < NCH; c += 2) {
            // iter A: consumers run MMA(c); we stage chunk c+1, start LDG c+2
            prefetch(c + 2, A0, B0);
            convert_store(c + 1, A1, B1);
            __syncthreads();
            // iter B: consumers run MMA(c+1); we stage chunk c+2, start LDG c+3
            if (c + 3 < NCH) prefetch(c + 3, A1, B1);
            convert_store(c + 2, A0, B0);
            __syncthreads();
        }

        // consumers run MMA(12); we publish rank-1 terms
        {
            float r = rt_acc + __shfl_xor_sync(0xffffffffu, rt_acc, 1);
            float q = ct_acc + __shfl_xor_sync(0xffffffffu, ct_acc, 1);
            if (phalf == 0) {
                rt_s[prow] = r;
                ct_s[prow] = q;
            }
        }
        __syncthreads();   // pairs with consumers' pre-epilogue barrier
        // done; consumers write the output
    } else {
        // ================= CONSUMER (warps 0..7) =================
        // 4(M) x 2(N) warps, warp tile 32x64
        const int warpMoff = (w & 3) * 32;
        const int warpNoff = (w >> 2) * 64;
        const int lr  = lane & 15;
        const int lkg = lane >> 4;

        float acc[2][8][4];
        #pragma unroll
        for (int mf = 0; mf < 2; mf++)
            #pragma unroll
            for (int nf = 0; nf < 8; nf++)
                #pragma unroll
                for (int i = 0; i < 4; i++) acc[mf][nf][i] = 0.f;

        auto mma_chunk = [&](int c) {
            const uint32_t st = smu + (uint32_t)(c & 1) * STAGE;
            #pragma unroll
            for (int ks = 0; ks < 2; ks++) {
                const uint32_t kgo = (uint32_t)(ks * 2 + lkg) * 16;
                uint32_t ah[2][4], al[2][4];
                #pragma unroll
                for (int mf = 0; mf < 2; mf++) {
                    const uint32_t off = (uint32_t)(warpMoff + mf * 16 + lr) * ROWB + kgo;
                    ldsm_x4(ah[mf][0], ah[mf][1], ah[mf][2], ah[mf][3], st + OFF_AHI + off);
                    ldsm_x4(al[mf][0], al[mf][1], al[mf][2], al[mf][3], st + OFF_ALO + off);
                }
                #pragma unroll
                for (int j = 0; j < 4; j++) {
                    uint32_t bh[4], bl[4];
                    const uint32_t off = (uint32_t)(warpNoff + j * 16 + lr) * ROWB + kgo;
                    ldsm_x4(bh[0], bh[1], bh[2], bh[3], st + OFF_BHI + off);
                    ldsm_x4(bl[0], bl[1], bl[2], bl[3], st + OFF_BLO + off);
                    #pragma unroll
                    for (int mf = 0; mf < 2; mf++) {
                        mma_bf16(acc[mf][2 * j],     ah[mf], bh[0], bh[2]);
                        mma_bf16(acc[mf][2 * j],     ah[mf], bl[0], bl[2]);
                        mma_bf16(acc[mf][2 * j],     al[mf], bh[0], bh[2]);
                        mma_bf16(acc[mf][2 * j + 1], ah[mf], bh[1], bh[3]);
                        mma_bf16(acc[mf][2 * j + 1], ah[mf], bl[1], bl[3]);
                        mma_bf16(acc[mf][2 * j + 1], al[mf], bh[1], bh[3]);
                    }
                }
            }
        };

        __syncthreads();   // pairs with producer prologue barrier

        for (int c = 0; c + 2 < NCH; c += 2) {
            mma_chunk(c);
            __syncthreads();
            mma_chunk(c + 1);
            __syncthreads();
        }
        mma_chunk(NCH - 1);
        __syncthreads();   // wait for rt_s / ct_s

        // ---- epilogue ----
        float* Cg = out + ((size_t)b * LC + rowTile) * LA + colTile;
        #pragma unroll
        for (int mf = 0; mf < 2; mf++) {
            const int r0 = warpMoff + mf * 16 + (lane >> 2);
            const int r1 = r0 + 8;
            const float rt0 = rt_s[r0], rt1 = rt_s[r1];
            #pragma unroll
            for (int nf = 0; nf < 8; nf++) {
                const int c0 = warpNoff + nf * 8 + (lane & 3) * 2;
                const float ct0 = ct_s[c0], ct1 = ct_s[c0 + 1];
                float2 v0 = make_float2(acc[mf][nf][0] + rt0 + ct0, acc[mf][nf][1] + rt0 + ct1);
                float2 v1 = make_float2(acc[mf][nf][2] + rt1 + ct0, acc[mf][nf][3] + rt1 + ct1);
                *(float2*)(Cg + (size_t)r0 * LA + c0) = v0;
                *(float2*)(Cg + (size_t)r1 * LA + c0) = v1;
            }
        }
    }
}

extern "C" void kernel_launch(void* const* d_in, const int* in_sizes, int n_in,
                              void* d_out, int out_size)
{
    const float* ctx = nullptr;
    const float* asp = nullptr;
    const float* w_u = nullptr;
    for (int i = 0; i < n_in; i++) {
        if (in_sizes[i] == NB * LC * DD)      ctx = (const float*)d_in[i];
        else if (in_sizes[i] == NB * LA * DD) asp = (const float*)d_in[i];
        else if (in_sizes[i] == 3 * DD)       w_u = (const float*)d_in[i];
    }
    float* out = (float*)d_out;

    cudaFuncSetAttribute(alignment_hmma_kernel,
                         cudaFuncAttributeMaxDynamicSharedMemorySize, SMEM_TOTAL);

    dim3 grid(LA / BN, LC / BM, NB);   // (4, 16, 64)
    alignment_hmma_kernel<<<grid, 512, SMEM_TOTAL>>>(ctx, asp, w_u, out);

    (void)out_size;
}

// round 17
// speedup vs baseline: 2.0995x; 1.0951x over previous
#include <cuda_runtime.h>
#include <cuda_bf16.h>
#include <cstdint>

#define DD 400
#define LC 2048
#define LA 512
#define NB 64

#define BM 128
#define BN 128
#define BK 32
#define NCH 13            // ceil(400/32) -> K padded to 416
#define KPAD 416

// smem layout (bytes). bf16 tiles with 80B row stride (64B data + 16B pad).
// 20-bank row stride => 8-row ldmatrix phases hit distinct bank groups.
#define ROWB 80
#define A_TILE (BM * ROWB)          // 10240
#define B_TILE (BN * ROWB)          // 10240
#define STAGE  (2 * A_TILE + 2 * B_TILE)   // 40960: Ahi, Alo, Bhi, Blo
#define OFF_AHI 0
#define OFF_ALO A_TILE
#define OFF_BHI (2 * A_TILE)
#define OFF_BLO (2 * A_TILE + B_TILE)
#define W_OFF   (2 * STAGE)                 // 81920
#define W_BYTES (KPAD * 4)                  // 1664 per vector
#define RT_OFF  (W_OFF + 3 * W_BYTES)       // 128 floats
#define CT_OFF  (RT_OFF + 512)              // 128 floats
#define SMEM_TOTAL (CT_OFF + 512)           // ~88KB -> 1 CTA/SM

__device__ __forceinline__ uint32_t smem_u32(const void* p) {
    uint32_t a;
    asm("{ .reg .u64 t; cvta.to.shared.u64 t, %1; cvt.u32.u64 %0, t; }" : "=r"(a) : "l"(p));
    return a;
}

__device__ __forceinline__ void ldsm_x4(uint32_t& r0, uint32_t& r1, uint32_t& r2, uint32_t& r3,
                                        uint32_t addr) {
    asm volatile("ldmatrix.sync.aligned.m8n8.x4.shared.b16 {%0,%1,%2,%3}, [%4];"
                 : "=r"(r0), "=r"(r1), "=r"(r2), "=r"(r3) : "r"(addr));
}

__device__ __forceinline__ void mma_bf16(float* d, const uint32_t* a, uint32_t b0, uint32_t b1) {
    asm volatile(
        "mma.sync.aligned.m16n8k16.row.col.f32.bf16.bf16.f32 "
        "{%0,%1,%2,%3}, {%4,%5,%6,%7}, {%8,%9}, {%0,%1,%2,%3};"
        : "+f"(d[0]), "+f"(d[1]), "+f"(d[2]), "+f"(d[3])
        : "r"(a[0]), "r"(a[1]), "r"(a[2]), "r"(a[3]), "r"(b0), "r"(b1));
}

__device__ __forceinline__ uint32_t packbf(float a, float b) {
    __nv_bfloat162 h = __floats2bfloat162_rn(a, b);
    return *reinterpret_cast<uint32_t*>(&h);
}

// split 4 floats into bf16 hi (uint2) and bf16 lo (uint2)
__device__ __forceinline__ void split4(const float4 f, uint2& hi, uint2& lo) {
    float h0 = __bfloat162float(__float2bfloat16(f.x));
    float h1 = __bfloat162float(__float2bfloat16(f.y));
    float h2 = __bfloat162float(__float2bfloat16(f.z));
    float h3 = __bfloat162float(__float2bfloat16(f.w));
    hi = make_uint2(packbf(h0, h1), packbf(h2, h3));
    lo = make_uint2(packbf(f.x - h0, f.y - h1), packbf(f.z - h2, f.w - h3));
}

__global__ __launch_bounds__(256, 1)
void alignment_hmma_kernel(const float* __restrict__ ctx,
                           const float* __restrict__ asp,
                           const float* __restrict__ w_u,
                           float* __restrict__ out)
{
    extern __shared__ char sm[];
    const uint32_t smu = smem_u32(sm);

    const int tid  = threadIdx.x;
    const int w    = tid >> 5;
    const int lane = tid & 31;
    const int b    = blockIdx.z;
    const int rowTile = blockIdx.y * BM;
    const int colTile = blockIdx.x * BN;

    float* w1s = (float*)(sm + W_OFF);
    float* w2s = (float*)(sm + W_OFF + W_BYTES);
    float* w3s = (float*)(sm + W_OFF + 2 * W_BYTES);
    float* rt_s = (float*)(sm + RT_OFF);
    float* ct_s = (float*)(sm + CT_OFF);

    for (int i = tid; i < KPAD; i += 256) {
        bool v = i < DD;
        w1s[i] = v ? w_u[i]          : 0.f;
        w2s[i] = v ? w_u[DD + i]     : 0.f;
        w3s[i] = v ? w_u[2 * DD + i] : 0.f;
    }
    __syncthreads();

    if (w >= 4) {
        // ================= PRODUCER (warps 4..7, 128 threads) =================
        // Coalesced: lane l of producer warp pw loads 16B seg (l&7) of rows
        // (pw*4 + (l>>3)) + 16*i, i=0..7.  Every LDG.128 covers 4 full lines.
        const int pw = w - 4;
        const int rowbase = pw * 4 + (lane >> 3);   // 0..15
        const int o = lane & 7;                      // 16B segment within 128B row-chunk
        const int ko = o * 4;                        // k offset within chunk

        const float* Abase = ctx + (size_t)b * LC * DD + (size_t)(rowTile + rowbase) * DD + ko;
        const float* Bbase = asp + (size_t)b * LA * DD + (size_t)(colTile + rowbase) * DD + ko;
        const uint32_t tSt = (uint32_t)(rowbase * ROWB + o * 8);   // bf16: 4 elems = 8B

        float rt_acc[8], ct_acc[8];
        #pragma unroll
        for (int i = 0; i < 8; i++) { rt_acc[i] = 0.f; ct_acc[i] = 0.f; }

        float4 A0[8], B0[8], A1[8], B1[8];

        auto prefetch = [&](int c, float4* A, float4* B) {
            const bool kv = (c * BK + ko) < DD;      // uniform over i
            #pragma unroll
            for (int i = 0; i < 8; i++) {
                A[i] = kv ? __ldg((const float4*)(Abase + (size_t)i * 16 * DD + c * BK))
                          : make_float4(0.f, 0.f, 0.f, 0.f);
                B[i] = kv ? __ldg((const float4*)(Bbase + (size_t)i * 16 * DD + c * BK))
                          : make_float4(0.f, 0.f, 0.f, 0.f);
            }
        };

        auto convert_store = [&](int c, const float4* A, const float4* B) {
            char* st = sm + (c & 1) * STAGE;
            const int kb = c * BK + ko;
            const float w1x = w1s[kb], w1y = w1s[kb + 1], w1z = w1s[kb + 2], w1w = w1s[kb + 3];
            const float w2x = w2s[kb], w2y = w2s[kb + 1], w2z = w2s[kb + 2], w2w = w2s[kb + 3];
            const float w3x = w3s[kb], w3y = w3s[kb + 1], w3z = w3s[kb + 2], w3w = w3s[kb + 3];
            #pragma unroll
            for (int i = 0; i < 8; i++) {
                const uint32_t rOff = tSt + (uint32_t)(i * 16 * ROWB);
                // A: fold w3, accumulate rt with w1
                float4 fa = A[i];
                rt_acc[i] += fa.x * w1x + fa.y * w1y + fa.z * w1z + fa.w * w1w;
                fa.x *= w3x; fa.y *= w3y; fa.z *= w3z; fa.w *= w3w;
                uint2 hi, lo;
                split4(fa, hi, lo);
                *(uint2*)(st + OFF_AHI + rOff) = hi;
                *(uint2*)(st + OFF_ALO + rOff) = lo;
                // B: accumulate ct with w2
                float4 fb = B[i];
                ct_acc[i] += fb.x * w2x + fb.y * w2y + fb.z * w2z + fb.w * w2w;
                split4(fb, hi, lo);
                *(uint2*)(st + OFF_BHI + rOff) = hi;
                *(uint2*)(st + OFF_BLO + rOff) = lo;
            }
        };

        prefetch(0, A0, B0);
        convert_store(0, A0, B0);
        prefetch(1, A1, B1);
        __syncthreads();

        for (int c = 0; c + 2 < NCH; c += 2) {
            prefetch(c + 2, A0, B0);
            convert_store(c + 1, A1, B1);
            __syncthreads();
            if (c + 3 < NCH) prefetch(c + 3, A1, B1);
            convert_store(c + 2, A0, B0);
            __syncthreads();
        }

        // reduce rank-1 partials over the 8 segment-lanes of each octet
        #pragma unroll
        for (int i = 0; i < 8; i++) {
            #pragma unroll
            for (int d = 1; d < 8; d <<= 1) {
                rt_acc[i] += __shfl_xor_sync(0xffffffffu, rt_acc[i], d);
                ct_acc[i] += __shfl_xor_sync(0xffffffffu, ct_acc[i], d);
            }
        }
        if (o == 0) {
            #pragma unroll
            for (int i = 0; i < 8; i++) {
                rt_s[rowbase + 16 * i] = rt_acc[i];
                ct_s[rowbase + 16 * i] = ct_acc[i];
            }
        }
        __syncthreads();   // pairs with consumers' pre-epilogue barrier
    } else {
        // ================= CONSUMER (warps 0..3) =================
        // 2(M) x 2(N) warps, warp tile 64x64 -> ldsm multiplicity 2x2
        const int warpMoff = (w & 1) * 64;
        const int warpNoff = (w >> 1) * 64;
        const int lr  = lane & 15;
        const int lkg = lane >> 4;

        float acc[4][8][4];
        #pragma unroll
        for (int mf = 0; mf < 4; mf++)
            #pragma unroll
            for (int nf = 0; nf < 8; nf++)
                #pragma unroll
                for (int i = 0; i < 4; i++) acc[mf][nf][i] = 0.f;

        auto mma_chunk = [&](int c) {
            const uint32_t st = smu + (uint32_t)(c & 1) * STAGE;
            #pragma unroll
            for (int ks = 0; ks < 2; ks++) {
                const uint32_t kgo = (uint32_t)(ks * 2 + lkg) * 16;
                uint32_t ah[4][4], al[4][4];
                #pragma unroll
                for (int mf = 0; mf < 4; mf++) {
                    const uint32_t off = (uint32_t)(warpMoff + mf * 16 + lr) * ROWB + kgo;
                    ldsm_x4(ah[mf][0], ah[mf][1], ah[mf][2], ah[mf][3], st + OFF_AHI + off);
                    ldsm_x4(al[mf][0], al[mf][1], al[mf][2], al[mf][3], st + OFF_ALO + off);
                }
                #pragma unroll
                for (int j = 0; j < 4; j++) {
                    uint32_t bh[4], bl[4];
                    const uint32_t off = (uint32_t)(warpNoff + j * 16 + lr) * ROWB + kgo;
                    ldsm_x4(bh[0], bh[1], bh[2], bh[3], st + OFF_BHI + off);
                    ldsm_x4(bl[0], bl[1], bl[2], bl[3], st + OFF_BLO + off);
                    #pragma unroll
                    for (int mf = 0; mf < 4; mf++) {
                        mma_bf16(acc[mf][2 * j],     ah[mf], bh[0], bh[2]);
                        mma_bf16(acc[mf][2 * j],     ah[mf], bl[0], bl[2]);
                        mma_bf16(acc[mf][2 * j],     al[mf], bh[0], bh[2]);
                        mma_bf16(acc[mf][2 * j + 1], ah[mf], bh[1], bh[3]);
                        mma_bf16(acc[mf][2 * j + 1], ah[mf], bl[1], bl[3]);
                        mma_bf16(acc[mf][2 * j + 1], al[mf], bh[1], bh[3]);
                    }
                }
            }
        };

        __syncthreads();   // pairs with producer prologue barrier

        for (int c = 0; c + 2 < NCH; c += 2) {
            mma_chunk(c);
            __syncthreads();
            mma_chunk(c + 1);
            __syncthreads();
        }
        mma_chunk(NCH - 1);
        __syncthreads();   // wait for rt_s / ct_s

        // ---- epilogue ----
        float* Cg = out + ((size_t)b * LC + rowTile) * LA + colTile;
        #pragma unroll
        for (int mf = 0; mf < 4; mf++) {
            const int r0 = warpMoff + mf * 16 + (lane >> 2);
            const int r1 = r0 + 8;
            const float rt0 = rt_s[r0], rt1 = rt_s[r1];
            #pragma unroll
            for (int nf = 0; nf < 8; nf++) {
                const int c0 = warpNoff + nf * 8 + (lane & 3) * 2;
                const float ct0 = ct_s[c0], ct1 = ct_s[c0 + 1];
                float2 v0 = make_float2(acc[mf][nf][0] + rt0 + ct0, acc[mf][nf][1] + rt0 + ct1);
                float2 v1 = make_float2(acc[mf][nf][2] + rt1 + ct0, acc[mf][nf][3] + rt1 + ct1);
                *(float2*)(Cg + (size_t)r0 * LA + c0) = v0;
                *(float2*)(Cg + (size_t)r1 * LA + c0) = v1;
            }
        }
    }
}

extern "C" void kernel_launch(void* const* d_in, const int* in_sizes, int n_in,
                              void* d_out, int out_size)
{
    const float* ctx = nullptr;
    const float* asp = nullptr;
    const float* w_u = nullptr;
    for (int i = 0; i < n_in; i++) {
        if (in_sizes[i] == NB * LC * DD)      ctx = (const float*)d_in[i];
        else if (in_sizes[i] == NB * LA * DD) asp = (const float*)d_in[i];
        else if (in_sizes[i] == 3 * DD)       w_u = (const float*)d_in[i];
    }
    float* out = (float*)d_out;

    cudaFuncSetAttribute(alignment_hmma_kernel,
                         cudaFuncAttributeMaxDynamicSharedMemorySize, SMEM_TOTAL);

    dim3 grid(LA / BN, LC / BM, NB);   // (4, 16, 64)
    alignment_hmma_kernel<<<grid, 256, SMEM_TOTAL>>>(ctx, asp, w_u, out);

    (void)out_size;
}